// round 2
// baseline (speedup 1.0000x reference)
#include <cuda_runtime.h>
#include <cstdint>

// ============================================================================
// VersorLinear on GB300:  y[b,o,k] = norm32( sum_{f,i} x[b,f,i] * W[o,f,i^k] * s(i,i^k) )
//
// Recast as ONE 4096x4096x4096 fp32 GEMM:
//   X   [4096 x 4096]  row-major, col index c = f*32+i  (== x's natural layout)
//   WpT [4096 x 4096]  row-major [c][n], n = o*32+k     (built by kernel A)
//   Y   [4096 x 4096]  row-major, col index n = o*32+k  (== output's natural layout)
// with a fused per-row 32-column-group normalization epilogue.
// fp32 math throughout; uses Blackwell packed fma.rn.f32x2 for 2x fp32 FMA issue width.
// ============================================================================

#define GA   32
#define NF   128
#define NBAT 4096
#define NC   4096   // reduction dim = NF*GA
#define NN   4096   // output cols   = NF*GA

// 64 MB scratch for the sign-twisted replicated weight (allocation-free rule:
// __device__ globals are the sanctioned scratch mechanism).
__device__ float g_WpT[(size_t)NC * NN];

// Cayley sign for Cl(4,1): C[a,b,a^b]. SIG = {+1,+1,+1,+1,-1} -> only bit 4 flips.
__device__ __forceinline__ float cayley_sign(int a, int b) {
    int s = 0;
    int aa = a >> 1;
    while (aa) { s += __popc(aa & b); aa >>= 1; }
    float sg = (s & 1) ? -1.0f : 1.0f;
    if ((a & b) & 16) sg = -sg;   // sig[4] = -1
    return sg;
}

// Kernel A: WpT[c][n] = W[o,f, i^k] * sign(i, i^k),  c=f*32+i, n=o*32+k
__global__ void build_wpt_kernel(const float* __restrict__ w) {
    int idx = blockIdx.x * blockDim.x + threadIdx.x;   // 0 .. 4096*4096-1
    int c = idx >> 12;
    int n = idx & 4095;
    int f = c >> 5, i = c & 31;
    int o = n >> 5, k = n & 31;
    int j = i ^ k;
    g_WpT[idx] = w[(o * NF + f) * GA + j] * cayley_sign(i, j);
}

// ============================================================================
// Kernel B: tiled GEMM + fused group-of-32 normalization
//   Block tile 128x128, K-tile 16, 256 threads, 8x8 per-thread microtile.
//   Accumulators packed as f32x2 pairs along columns (fma.rn.f32x2).
// ============================================================================
#define BM 128
#define BN 128
#define BK 16

__global__ __launch_bounds__(256, 2)
void gemm_norm_kernel(const float* __restrict__ X, float* __restrict__ Y) {
    __shared__ float As[BK][BM + 4];   // [k][m], transposed on store
    __shared__ float Bs[BK][BN];       // [k][n], natural

    const int tid = threadIdx.x;
    const int tx  = tid & 15;          // column group within tile
    const int ty  = tid >> 4;          // row group within tile
    const int bm  = blockIdx.y * BM;
    const int bn  = blockIdx.x * BN;

    // A tile loads: 128 rows x 16 cols as float4 along K, transposed into smem.
    const int ar = tid >> 2;           // 0..63 (and +64)
    const int ac = (tid & 3) * 4;      // 0,4,8,12
    // B tile loads: 16 rows x 128 cols as float4 along N (fully coalesced).
    const int br = tid >> 4;           // 0..15
    const int bc = (tid & 15) * 4;     // 0..60 (and +64)

    const float* Ag = X + (size_t)bm * NC;
    const float* Bg = g_WpT + bn;

    // prefetch tile 0 into registers
    float4 a0 = *(const float4*)(Ag + (size_t)ar        * NC + ac);
    float4 a1 = *(const float4*)(Ag + (size_t)(ar + 64) * NC + ac);
    float4 b0 = *(const float4*)(Bg + (size_t)br * NN + bc);
    float4 b1 = *(const float4*)(Bg + (size_t)br * NN + bc + 64);

    // 8x8 accumulators as 8x4 packed f32x2 (pair = adjacent columns)
    unsigned long long acc[8][4];
#pragma unroll
    for (int r = 0; r < 8; r++)
#pragma unroll
        for (int c2 = 0; c2 < 4; c2++) acc[r][c2] = 0ull;

    const int NT = NC / BK;            // 256 K-tiles
    for (int t = 0; t < NT; t++) {
        // smem stores (prev compute finished at trailing __syncthreads)
        As[ac + 0][ar]      = a0.x; As[ac + 1][ar]      = a0.y;
        As[ac + 2][ar]      = a0.z; As[ac + 3][ar]      = a0.w;
        As[ac + 0][ar + 64] = a1.x; As[ac + 1][ar + 64] = a1.y;
        As[ac + 2][ar + 64] = a1.z; As[ac + 3][ar + 64] = a1.w;
        *(float4*)(&Bs[br][bc])      = b0;
        *(float4*)(&Bs[br][bc + 64]) = b1;
        __syncthreads();

        // prefetch next tile while computing this one
        if (t + 1 < NT) {
            const float* Ag2 = Ag + (t + 1) * BK;
            const float* Bg2 = Bg + (size_t)(t + 1) * BK * NN;
            a0 = *(const float4*)(Ag2 + (size_t)ar        * NC + ac);
            a1 = *(const float4*)(Ag2 + (size_t)(ar + 64) * NC + ac);
            b0 = *(const float4*)(Bg2 + (size_t)br * NN + bc);
            b1 = *(const float4*)(Bg2 + (size_t)br * NN + bc + 64);
        }

#pragma unroll
        for (int kk = 0; kk < BK; kk++) {
            float4 af0 = *(const float4*)(&As[kk][ty * 8]);
            float4 af1 = *(const float4*)(&As[kk][ty * 8 + 4]);
            // B pairs read directly as 64-bit (8-byte aligned: tx*8 floats = 32B)
            const unsigned long long* bp =
                (const unsigned long long*)(&Bs[kk][tx * 8]);
            unsigned long long bq0 = bp[0], bq1 = bp[1], bq2 = bp[2], bq3 = bp[3];

            float av[8] = {af0.x, af0.y, af0.z, af0.w, af1.x, af1.y, af1.z, af1.w};
#pragma unroll
            for (int r = 0; r < 8; r++) {
                unsigned long long a2;
                asm("mov.b64 %0, {%1, %1};"
                    : "=l"(a2) : "r"(__float_as_uint(av[r])));
                asm("fma.rn.f32x2 %0, %1, %2, %0;" : "+l"(acc[r][0]) : "l"(a2), "l"(bq0));
                asm("fma.rn.f32x2 %0, %1, %2, %0;" : "+l"(acc[r][1]) : "l"(a2), "l"(bq1));
                asm("fma.rn.f32x2 %0, %1, %2, %0;" : "+l"(acc[r][2]) : "l"(a2), "l"(bq2));
                asm("fma.rn.f32x2 %0, %1, %2, %0;" : "+l"(acc[r][3]) : "l"(a2), "l"(bq3));
            }
        }
        __syncthreads();
    }

    // ---- Fused epilogue: normalize each 32-column group per row ----
    // This thread's 8 columns (tx*8 .. tx*8+7) lie inside ONE 32-col group;
    // the 4 threads covering the group differ only in tx bits 0..1 ->
    // warp lanes lane^1, lane^2. Two butterflies give the group sum.
#pragma unroll
    for (int r = 0; r < 8; r++) {
        float v[8];
#pragma unroll
        for (int c2 = 0; c2 < 4; c2++) {
            unsigned int lo, hi;
            asm("mov.b64 {%0, %1}, %2;" : "=r"(lo), "=r"(hi) : "l"(acc[r][c2]));
            v[2 * c2]     = __uint_as_float(lo);
            v[2 * c2 + 1] = __uint_as_float(hi);
        }
        float s = 0.0f;
#pragma unroll
        for (int c = 0; c < 8; c++) s += v[c] * v[c];
        s += __shfl_xor_sync(0xffffffffu, s, 1);
        s += __shfl_xor_sync(0xffffffffu, s, 2);
        float inv = rsqrtf(s + 1e-6f);

        float4 o0 = make_float4(v[0] * inv, v[1] * inv, v[2] * inv, v[3] * inv);
        float4 o1 = make_float4(v[4] * inv, v[5] * inv, v[6] * inv, v[7] * inv);
        size_t row = (size_t)(bm + ty * 8 + r);
        float* yp = Y + row * NN + bn + tx * 8;
        *(float4*)(yp)     = o0;
        *(float4*)(yp + 4) = o1;
    }
}

// ============================================================================
extern "C" void kernel_launch(void* const* d_in, const int* in_sizes, int n_in,
                              void* d_out, int out_size) {
    const float* x = (const float*)d_in[0];
    const float* w = (const float*)d_in[1];
    // defensive: x has 4096*128*32 elems, w has 128*128*32
    if (n_in >= 2 && in_sizes[0] == NF * NF * GA && in_sizes[1] != NF * NF * GA) {
        const float* t = x; x = w; w = t;
    }
    float* y = (float*)d_out;

    build_wpt_kernel<<<(NC * NN) / 256, 256>>>(w);

    dim3 grid(NN / BN, NBAT / BM);   // (32, 32)
    gemm_norm_kernel<<<grid, 256>>>(x, y);
}

// round 10
// speedup vs baseline: 2.3721x; 2.3721x over previous
#include <cuda_runtime.h>
#include <cstdint>

// ============================================================================
// VersorLinear = one 4096x4096x4096 tf32 GEMM + fused 32-col-group normalize.
//   Y[4096x4096] = Xr * WpT^T,  WpT[n][c] K-major, n=o*32+k, c=f*32+i
//   WpT[n][c] = W[o,f,i^k]*sign(i,i^k)   (both operands tf32-rounded, rna)
// Executed with warp-level mma.sync.m16n8k8.tf32 (family-stable; tcgen05 is
// rejected by this bench's compute_103 PTX target) + ldmatrix.x4 fragment
// loads + 2-stage cp.async pipeline.
// FIX vs last round: __device__ globals are referenced inside device code,
// never passed as host-side kernel arguments (host &devsym is invalid).
// ============================================================================

#define GA   32
#define NF   128
#define NBAT 4096
#define NC   4096
#define NN   4096

#define BM 128
#define BN 256
#define BK 32
#define NT (NC / BK)          // 128

#define ASTR   36             // floats per smem row (32 + 4 pad)
#define A_BYTES (BM * ASTR * 4)          // 18432
#define B_BYTES (BN * ASTR * 4)          // 36864
#define STAGE_BYTES (A_BYTES + B_BYTES)  // 55296
#define SMEM_DYN (2 * STAGE_BYTES)       // 110592

__device__ float g_WpT[(size_t)NN * NC];   // 64 MB sign-twisted weight (tf32 bits)
__device__ float g_Xr [(size_t)NBAT * NC]; // 64 MB tf32-rounded x

// ---------------------------------------------------------------------------
__device__ __forceinline__ float cayley_sign(int a, int b) {
    int s = 0;
    int aa = a >> 1;
    while (aa) { s += __popc(aa & b); aa >>= 1; }
    float sg = (s & 1) ? -1.0f : 1.0f;
    if ((a & b) & 16) sg = -sg;            // sig[4] = -1
    return sg;
}
__device__ __forceinline__ uint32_t to_tf32(float x) {
    uint32_t u;
    asm("cvt.rna.tf32.f32 %0, %1;" : "=r"(u) : "f"(x));
    return u;
}

__global__ void build_wpt(const float* __restrict__ w) {
    int idx = blockIdx.x * blockDim.x + threadIdx.x;
    int n = idx >> 12, c = idx & 4095;
    int o = n >> 5, k = n & 31, f = c >> 5, i = c & 31;
    int j = i ^ k;
    float v = w[(o * NF + f) * GA + j] * cayley_sign(i, j);
    reinterpret_cast<uint32_t*>(g_WpT)[idx] = to_tf32(v);
}

__global__ void conv_x(const float* __restrict__ x) {
    int idx = blockIdx.x * blockDim.x + threadIdx.x;   // over float4s
    float4 v = reinterpret_cast<const float4*>(x)[idx];
    uint4 r;
    r.x = to_tf32(v.x); r.y = to_tf32(v.y);
    r.z = to_tf32(v.z); r.w = to_tf32(v.w);
    reinterpret_cast<uint4*>(g_Xr)[idx] = r;
}

// ---------------------------------------------------------------------------
__device__ __forceinline__ uint32_t smem_u32(const void* p) {
    uint32_t a;
    asm("{ .reg .u64 t; cvta.to.shared.u64 t, %1; cvt.u32.u64 %0, t; }"
        : "=r"(a) : "l"(p));
    return a;
}
__device__ __forceinline__ void cpa16(uint32_t dst, const void* src) {
    asm volatile("cp.async.cg.shared.global [%0], [%1], 16;"
                 :: "r"(dst), "l"(src) : "memory");
}
__device__ __forceinline__ void ldsm4(uint32_t* r, uint32_t addr) {
    asm volatile("ldmatrix.sync.aligned.m8n8.x4.shared.b16 {%0,%1,%2,%3}, [%4];"
                 : "=r"(r[0]), "=r"(r[1]), "=r"(r[2]), "=r"(r[3]) : "r"(addr));
}
// D += A*B  (m16n8k8 tf32). PTX order {a0,a1,a2,a3} = ldsm regs {0,2,1,3}.
__device__ __forceinline__ void mma8(float* c, const uint32_t* a,
                                     uint32_t b0, uint32_t b1) {
    asm volatile(
        "mma.sync.aligned.m16n8k8.row.col.f32.tf32.tf32.f32 "
        "{%0,%1,%2,%3}, {%4,%5,%6,%7}, {%8,%9}, {%0,%1,%2,%3};"
        : "+f"(c[0]), "+f"(c[1]), "+f"(c[2]), "+f"(c[3])
        : "r"(a[0]), "r"(a[2]), "r"(a[1]), "r"(a[3]), "r"(b0), "r"(b1));
}

// ---------------------------------------------------------------------------
__global__ __launch_bounds__(512, 1)
void gemm_mma(float* __restrict__ Y) {
    extern __shared__ char dsm[];
    const uint32_t smb = smem_u32(dsm);

    const float* __restrict__ X  = g_Xr;     // device-side symbol refs (valid)
    const float* __restrict__ Wt = g_WpT;

    const int tid    = threadIdx.x;
    const int wid    = tid >> 5;
    const int lane   = tid & 31;
    const int warp_m = wid >> 2;          // 0..3 -> 32-row strips
    const int warp_n = wid & 3;           // 0..3 -> 64-col strips
    const int bm     = blockIdx.y * BM;
    const int bn     = blockIdx.x * BN;

    // ldmatrix per-lane address components (lane j: matrix q=j/8, row r=j%8)
    const int qa     = lane >> 3;                       // 0..3
    const int rowoff = (lane & 7) + ((qa >> 1) << 3);   // row within 16
    const int choff  = (qa & 1) * 16;                   // fp32 cols 0-3 vs 4-7
    const uint32_t offA = (uint32_t)(warp_m * 32 + rowoff) * (ASTR * 4) + choff;
    const uint32_t offB = (uint32_t)(warp_n * 64 + rowoff) * (ASTR * 4) + choff;

    float c[2][8][4];
#pragma unroll
    for (int mt = 0; mt < 2; mt++)
#pragma unroll
        for (int nt = 0; nt < 8; nt++)
#pragma unroll
            for (int q = 0; q < 4; q++) c[mt][nt][q] = 0.0f;

    auto load_tile = [&](int t, int s) {
        const uint32_t sa = smb + s * STAGE_BYTES;
        const uint32_t sb = sa + A_BYTES;
        const float* Ag = X  + (size_t)bm * NC + t * BK;
        const float* Bg = Wt + (size_t)bn * NC + t * BK;
#pragma unroll
        for (int q = 0; q < 2; q++) {               // A: 128 rows x 8 chunks
            int idx = tid + 512 * q;
            int row = idx >> 3, ch = idx & 7;
            cpa16(sa + row * (ASTR * 4) + ch * 16,
                  Ag + (size_t)row * NC + ch * 4);
        }
#pragma unroll
        for (int q = 0; q < 4; q++) {               // B: 256 rows x 8 chunks
            int idx = tid + 512 * q;
            int row = idx >> 3, ch = idx & 7;
            cpa16(sb + row * (ASTR * 4) + ch * 16,
                  Bg + (size_t)row * NC + ch * 4);
        }
    };

    load_tile(0, 0);
    asm volatile("cp.async.commit_group;" ::: "memory");

    for (int t = 0; t < NT; t++) {
        const int cur = t & 1;
        if (t + 1 < NT) load_tile(t + 1, cur ^ 1);
        asm volatile("cp.async.commit_group;" ::: "memory");
        if (t + 1 < NT) asm volatile("cp.async.wait_group 1;" ::: "memory");
        else            asm volatile("cp.async.wait_group 0;" ::: "memory");
        __syncthreads();

        const uint32_t sa = smb + cur * STAGE_BYTES;
        const uint32_t sb = sa + A_BYTES;
#pragma unroll
        for (int ks = 0; ks < 4; ks++) {            // 4 x k8 steps
            uint32_t a[2][4];
#pragma unroll
            for (int mt = 0; mt < 2; mt++)
                ldsm4(a[mt], sa + offA + mt * (16 * ASTR * 4) + ks * 32);
#pragma unroll
            for (int p = 0; p < 4; p++) {           // 4 n-pairs (16 cols each)
                uint32_t b[4];
                ldsm4(b, sb + offB + p * (16 * ASTR * 4) + ks * 32);
#pragma unroll
                for (int mt = 0; mt < 2; mt++) {
                    mma8(c[mt][2 * p],     a[mt], b[0], b[1]);
                    mma8(c[mt][2 * p + 1], a[mt], b[2], b[3]);
                }
            }
        }
        __syncthreads();
    }

    // ---- fused epilogue: normalize each aligned 32-col group per row ----
#pragma unroll
    for (int mt = 0; mt < 2; mt++) {
#pragma unroll
        for (int rr = 0; rr < 2; rr++) {
            const int row = bm + warp_m * 32 + mt * 16 + rr * 8 + (lane >> 2);
            float* yrow = Y + (size_t)row * NN + bn + warp_n * 64;
#pragma unroll
            for (int g = 0; g < 2; g++) {           // two 32-col groups
                float s = 0.0f;
#pragma unroll
                for (int q = 0; q < 4; q++) {
                    const float v0 = c[mt][g * 4 + q][rr * 2];
                    const float v1 = c[mt][g * 4 + q][rr * 2 + 1];
                    s = fmaf(v0, v0, fmaf(v1, v1, s));
                }
                s += __shfl_xor_sync(0xffffffffu, s, 1);
                s += __shfl_xor_sync(0xffffffffu, s, 2);
                const float inv = rsqrtf(s + 1e-6f);
#pragma unroll
                for (int q = 0; q < 4; q++) {
                    const int nt = g * 4 + q;
                    float2 o;
                    o.x = c[mt][nt][rr * 2]     * inv;
                    o.y = c[mt][nt][rr * 2 + 1] * inv;
                    *reinterpret_cast<float2*>(yrow + nt * 8 + 2 * (lane & 3)) = o;
                }
            }
        }
    }
}

// ============================================================================
extern "C" void kernel_launch(void* const* d_in, const int* in_sizes, int n_in,
                              void* d_out, int out_size) {
    const float* x = (const float*)d_in[0];
    const float* w = (const float*)d_in[1];
    if (n_in >= 2 && in_sizes[0] == NF * NF * GA && in_sizes[1] != NF * NF * GA) {
        const float* t = x; x = w; w = t;
    }
    float* y = (float*)d_out;

    build_wpt<<<(NN * NC) / 256, 256>>>(w);
    conv_x<<<(NBAT * NC / 4) / 256, 256>>>(x);

    cudaFuncSetAttribute(gemm_mma, cudaFuncAttributeMaxDynamicSharedMemorySize,
                         SMEM_DYN);
    dim3 grid(NN / BN, NBAT / BM);   // (16, 32)
    gemm_mma<<<grid, 512, SMEM_DYN>>>(y);
}

// round 11
// speedup vs baseline: 2.4905x; 1.0499x over previous
#include <cuda_runtime.h>
#include <cstdint>

// ============================================================================
// VersorLinear = one 4096x4096x4096 tf32 GEMM + fused 32-col-group normalize.
//   Y = Xr * WpT^T,  WpT[n][c] K-major, n=o*32+k, c=f*32+i
//   WpT[n][c] = W[o,f,i^k]*sign(i,i^k)   (both operands tf32-rounded, rna)
// mma.sync.m16n8k8.tf32 + ldmatrix.x4 + THREE-stage cp.async pipeline with a
// single __syncthreads per mainloop iteration (was 2-stage / 2 syncs).
// ============================================================================

#define GA   32
#define NF   128
#define NBAT 4096
#define NC   4096
#define NN   4096

#define BM 128
#define BN 256
#define BK 32
#define NT (NC / BK)          // 128
#define STAGES 3

#define ASTR   36             // floats per smem row (32 + 4 pad)
#define A_BYTES (BM * ASTR * 4)          // 18432
#define B_BYTES (BN * ASTR * 4)          // 36864
#define STAGE_BYTES (A_BYTES + B_BYTES)  // 55296
#define SMEM_DYN (STAGES * STAGE_BYTES)  // 165888

__device__ float g_WpT[(size_t)NN * NC];   // 64 MB sign-twisted weight (tf32 bits)
__device__ float g_Xr [(size_t)NBAT * NC]; // 64 MB tf32-rounded x

// ---------------------------------------------------------------------------
__device__ __forceinline__ float cayley_sign(int a, int b) {
    int s = 0;
    int aa = a >> 1;
    while (aa) { s += __popc(aa & b); aa >>= 1; }
    float sg = (s & 1) ? -1.0f : 1.0f;
    if ((a & b) & 16) sg = -sg;            // sig[4] = -1
    return sg;
}
__device__ __forceinline__ uint32_t to_tf32(float x) {
    uint32_t u;
    asm("cvt.rna.tf32.f32 %0, %1;" : "=r"(u) : "f"(x));
    return u;
}

__global__ void build_wpt(const float* __restrict__ w) {
    int idx = blockIdx.x * blockDim.x + threadIdx.x;
    int n = idx >> 12, c = idx & 4095;
    int o = n >> 5, k = n & 31, f = c >> 5, i = c & 31;
    int j = i ^ k;
    float v = w[(o * NF + f) * GA + j] * cayley_sign(i, j);
    reinterpret_cast<uint32_t*>(g_WpT)[idx] = to_tf32(v);
}

__global__ void conv_x(const float* __restrict__ x) {
    int idx = blockIdx.x * blockDim.x + threadIdx.x;   // over float4s
    float4 v = reinterpret_cast<const float4*>(x)[idx];
    uint4 r;
    r.x = to_tf32(v.x); r.y = to_tf32(v.y);
    r.z = to_tf32(v.z); r.w = to_tf32(v.w);
    reinterpret_cast<uint4*>(g_Xr)[idx] = r;
}

// ---------------------------------------------------------------------------
__device__ __forceinline__ uint32_t smem_u32(const void* p) {
    uint32_t a;
    asm("{ .reg .u64 t; cvta.to.shared.u64 t, %1; cvt.u32.u64 %0, t; }"
        : "=r"(a) : "l"(p));
    return a;
}
__device__ __forceinline__ void cpa16(uint32_t dst, const void* src) {
    asm volatile("cp.async.cg.shared.global [%0], [%1], 16;"
                 :: "r"(dst), "l"(src) : "memory");
}
__device__ __forceinline__ void ldsm4(uint32_t* r, uint32_t addr) {
    asm volatile("ldmatrix.sync.aligned.m8n8.x4.shared.b16 {%0,%1,%2,%3}, [%4];"
                 : "=r"(r[0]), "=r"(r[1]), "=r"(r[2]), "=r"(r[3]) : "r"(addr));
}
// D += A*B  (m16n8k8 tf32). PTX order {a0,a1,a2,a3} = ldsm regs {0,2,1,3}.
__device__ __forceinline__ void mma8(float* c, const uint32_t* a,
                                     uint32_t b0, uint32_t b1) {
    asm volatile(
        "mma.sync.aligned.m16n8k8.row.col.f32.tf32.tf32.f32 "
        "{%0,%1,%2,%3}, {%4,%5,%6,%7}, {%8,%9}, {%0,%1,%2,%3};"
        : "+f"(c[0]), "+f"(c[1]), "+f"(c[2]), "+f"(c[3])
        : "r"(a[0]), "r"(a[2]), "r"(a[1]), "r"(a[3]), "r"(b0), "r"(b1));
}

// ---------------------------------------------------------------------------
__global__ __launch_bounds__(512, 1)
void gemm_mma(float* __restrict__ Y) {
    extern __shared__ char dsm[];
    const uint32_t smb = smem_u32(dsm);

    const float* __restrict__ X  = g_Xr;
    const float* __restrict__ Wt = g_WpT;

    const int tid    = threadIdx.x;
    const int wid    = tid >> 5;
    const int lane   = tid & 31;
    const int warp_m = wid >> 2;          // 0..3 -> 32-row strips
    const int warp_n = wid & 3;           // 0..3 -> 64-col strips
    const int bm     = blockIdx.y * BM;
    const int bn     = blockIdx.x * BN;

    // ldmatrix per-lane address components
    const int qa     = lane >> 3;                       // 0..3
    const int rowoff = (lane & 7) + ((qa >> 1) << 3);   // row within 16
    const int choff  = (qa & 1) * 16;                   // fp32 cols 0-3 vs 4-7
    const uint32_t offA = (uint32_t)(warp_m * 32 + rowoff) * (ASTR * 4) + choff;
    const uint32_t offB = (uint32_t)(warp_n * 64 + rowoff) * (ASTR * 4) + choff;

    float c[2][8][4];
#pragma unroll
    for (int mt = 0; mt < 2; mt++)
#pragma unroll
        for (int nt = 0; nt < 8; nt++)
#pragma unroll
            for (int q = 0; q < 4; q++) c[mt][nt][q] = 0.0f;

    auto load_tile = [&](int t, int s) {
        const uint32_t sa = smb + s * STAGE_BYTES;
        const uint32_t sb = sa + A_BYTES;
        const float* Ag = X  + (size_t)bm * NC + t * BK;
        const float* Bg = Wt + (size_t)bn * NC + t * BK;
#pragma unroll
        for (int q = 0; q < 2; q++) {               // A: 128 rows x 8 chunks
            int idx = tid + 512 * q;
            int row = idx >> 3, ch = idx & 7;
            cpa16(sa + row * (ASTR * 4) + ch * 16,
                  Ag + (size_t)row * NC + ch * 4);
        }
#pragma unroll
        for (int q = 0; q < 4; q++) {               // B: 256 rows x 8 chunks
            int idx = tid + 512 * q;
            int row = idx >> 3, ch = idx & 7;
            cpa16(sb + row * (ASTR * 4) + ch * 16,
                  Bg + (size_t)row * NC + ch * 4);
        }
    };

    // prologue: tiles 0 and 1 into stages 0 and 1
    load_tile(0, 0);
    asm volatile("cp.async.commit_group;" ::: "memory");
    load_tile(1, 1);
    asm volatile("cp.async.commit_group;" ::: "memory");

    int cur = 0;                                    // stage of tile t
    int nxt = 2;                                    // stage for tile t+2
    for (int t = 0; t < NT; t++) {
        // tile t resident (newest group tile t+1 may still be in flight)
        asm volatile("cp.async.wait_group 1;" ::: "memory");
        __syncthreads();        // all warps done with stage 'nxt' (tile t-1)

        if (t + 2 < NT) load_tile(t + 2, nxt);
        asm volatile("cp.async.commit_group;" ::: "memory");  // may be empty

        const uint32_t sa = smb + cur * STAGE_BYTES;
        const uint32_t sb = sa + A_BYTES;
#pragma unroll
        for (int ks = 0; ks < 4; ks++) {            // 4 x k8 steps
            uint32_t a[2][4];
#pragma unroll
            for (int mt = 0; mt < 2; mt++)
                ldsm4(a[mt], sa + offA + mt * (16 * ASTR * 4) + ks * 32);
#pragma unroll
            for (int p = 0; p < 4; p++) {           // 4 n-pairs (16 cols each)
                uint32_t b[4];
                ldsm4(b, sb + offB + p * (16 * ASTR * 4) + ks * 32);
#pragma unroll
                for (int mt = 0; mt < 2; mt++) {
                    mma8(c[mt][2 * p],     a[mt], b[0], b[1]);
                    mma8(c[mt][2 * p + 1], a[mt], b[2], b[3]);
                }
            }
        }
        cur = (cur == STAGES - 1) ? 0 : cur + 1;
        nxt = (nxt == STAGES - 1) ? 0 : nxt + 1;
    }

    // ---- fused epilogue: normalize each aligned 32-col group per row ----
#pragma unroll
    for (int mt = 0; mt < 2; mt++) {
#pragma unroll
        for (int rr = 0; rr < 2; rr++) {
            const int row = bm + warp_m * 32 + mt * 16 + rr * 8 + (lane >> 2);
            float* yrow = Y + (size_t)row * NN + bn + warp_n * 64;
#pragma unroll
            for (int g = 0; g < 2; g++) {           // two 32-col groups
                float s = 0.0f;
#pragma unroll
                for (int q = 0; q < 4; q++) {
                    const float v0 = c[mt][g * 4 + q][rr * 2];
                    const float v1 = c[mt][g * 4 + q][rr * 2 + 1];
                    s = fmaf(v0, v0, fmaf(v1, v1, s));
                }
                s += __shfl_xor_sync(0xffffffffu, s, 1);
                s += __shfl_xor_sync(0xffffffffu, s, 2);
                const float inv = rsqrtf(s + 1e-6f);
#pragma unroll
                for (int q = 0; q < 4; q++) {
                    const int nt = g * 4 + q;
                    float2 o;
                    o.x = c[mt][nt][rr * 2]     * inv;
                    o.y = c[mt][nt][rr * 2 + 1] * inv;
                    *reinterpret_cast<float2*>(yrow + nt * 8 + 2 * (lane & 3)) = o;
                }
            }
        }
    }
}

// ============================================================================
extern "C" void kernel_launch(void* const* d_in, const int* in_sizes, int n_in,
                              void* d_out, int out_size) {
    const float* x = (const float*)d_in[0];
    const float* w = (const float*)d_in[1];
    if (n_in >= 2 && in_sizes[0] == NF * NF * GA && in_sizes[1] != NF * NF * GA) {
        const float* t = x; x = w; w = t;
    }
    float* y = (float*)d_out;

    build_wpt<<<(NN * NC) / 256, 256>>>(w);
    conv_x<<<(NBAT * NC / 4) / 256, 256>>>(x);

    cudaFuncSetAttribute(gemm_mma, cudaFuncAttributeMaxDynamicSharedMemorySize,
                         SMEM_DYN);
    dim3 grid(NN / BN, NBAT / BM);   // (16, 32)
    gemm_mma<<<grid, 512, SMEM_DYN>>>(y);
}